// round 1
// baseline (speedup 1.0000x reference)
#include <cuda_runtime.h>
#include <cstddef>

#define SEQ 4096
#define DMODEL 1024

// Scratch (allocation-free rule: device globals)
__device__ float g_Q[(size_t)SEQ * DMODEL];
__device__ float g_K[(size_t)SEQ * DMODEL];
__device__ float g_V[(size_t)SEQ * DMODEL];
__device__ float g_S[(size_t)SEQ * SEQ];

// ---------------------------------------------------------------------------
// Tiled SGEMM: C[M,N] = A[M,K] @ op(B)
//   TRANS_B = false: B is [K,N] row-major (NN)
//   TRANS_B = true : B is [N,K] row-major (NT), C[m,n] = sum_k A[m,k]*B[n,k]
// Tile: 128x128x16, 256 threads, 8x8 accum per thread.
// Requires M%128==0, N%128==0, K%16==0 (true for all shapes here).
// ---------------------------------------------------------------------------
template <bool TRANS_B>
__global__ __launch_bounds__(256) void sgemm_kernel(
    const float* __restrict__ A, const float* __restrict__ B,
    float* __restrict__ C, int M, int N, int K)
{
    constexpr int BM = 128, BN = 128, BK = 16;
    __shared__ float As[BK][BM + 4];
    __shared__ float Bs[BK][BN + 4];

    const int tid = threadIdx.x;
    const int bx = blockIdx.x;   // N tile
    const int by = blockIdx.y;   // M tile

    const int tr = tid >> 4;     // 0..15 (row group)
    const int tc = tid & 15;     // 0..15 (col group)

    // A load indices: 128 rows x 16 cols, float4 per thread, 2 iters
    const int a_row = tid >> 2;          // 0..63
    const int a_col = (tid & 3) * 4;     // 0,4,8,12

    // B load indices (NN): 16 rows x 128 cols
    const int b_row = tid >> 5;          // 0..7
    const int b_col = (tid & 31) * 4;    // 0..124

    float acc[8][8];
#pragma unroll
    for (int i = 0; i < 8; i++)
#pragma unroll
        for (int j = 0; j < 8; j++) acc[i][j] = 0.0f;

    for (int kt = 0; kt < K; kt += BK) {
        // --- load A tile (transposed into smem) ---
#pragma unroll
        for (int it = 0; it < 2; it++) {
            int r = a_row + it * 64;
            float4 v = *reinterpret_cast<const float4*>(
                &A[(size_t)(by * BM + r) * K + kt + a_col]);
            As[a_col + 0][r] = v.x;
            As[a_col + 1][r] = v.y;
            As[a_col + 2][r] = v.z;
            As[a_col + 3][r] = v.w;
        }
        // --- load B tile ---
        if (!TRANS_B) {
#pragma unroll
            for (int it = 0; it < 2; it++) {
                int r = b_row + it * 8;
                float4 v = *reinterpret_cast<const float4*>(
                    &B[(size_t)(kt + r) * N + bx * BN + b_col]);
                *reinterpret_cast<float4*>(&Bs[r][b_col]) = v;
            }
        } else {
            // B is [N,K]; Bs[k][n] = B[bx*128+n][kt+k]
#pragma unroll
            for (int it = 0; it < 2; it++) {
                int n = a_row + it * 64;
                float4 v = *reinterpret_cast<const float4*>(
                    &B[(size_t)(bx * BN + n) * K + kt + a_col]);
                Bs[a_col + 0][n] = v.x;
                Bs[a_col + 1][n] = v.y;
                Bs[a_col + 2][n] = v.z;
                Bs[a_col + 3][n] = v.w;
            }
        }
        __syncthreads();

        // --- compute ---
#pragma unroll
        for (int kk = 0; kk < BK; kk++) {
            float ra[8], rb[8];
            float4 a0 = *reinterpret_cast<const float4*>(&As[kk][tr * 8 + 0]);
            float4 a1 = *reinterpret_cast<const float4*>(&As[kk][tr * 8 + 4]);
            float4 b0 = *reinterpret_cast<const float4*>(&Bs[kk][tc * 8 + 0]);
            float4 b1 = *reinterpret_cast<const float4*>(&Bs[kk][tc * 8 + 4]);
            ra[0] = a0.x; ra[1] = a0.y; ra[2] = a0.z; ra[3] = a0.w;
            ra[4] = a1.x; ra[5] = a1.y; ra[6] = a1.z; ra[7] = a1.w;
            rb[0] = b0.x; rb[1] = b0.y; rb[2] = b0.z; rb[3] = b0.w;
            rb[4] = b1.x; rb[5] = b1.y; rb[6] = b1.z; rb[7] = b1.w;
#pragma unroll
            for (int i = 0; i < 8; i++)
#pragma unroll
                for (int j = 0; j < 8; j++)
                    acc[i][j] = fmaf(ra[i], rb[j], acc[i][j]);
        }
        __syncthreads();
    }

    // --- write back ---
#pragma unroll
    for (int i = 0; i < 8; i++) {
        size_t row = (size_t)(by * BM + tr * 8 + i);
#pragma unroll
        for (int j = 0; j < 8; j += 4) {
            float4 v;
            v.x = acc[i][j + 0];
            v.y = acc[i][j + 1];
            v.z = acc[i][j + 2];
            v.w = acc[i][j + 3];
            *reinterpret_cast<float4*>(&C[row * N + bx * BN + tc * 8 + j]) = v;
        }
    }
}

// ---------------------------------------------------------------------------
// Fused scale + softmax over each row of S [SEQ, SEQ], in place.
// One block (256 threads) per row; 16 elements per thread, register resident.
// ---------------------------------------------------------------------------
__global__ __launch_bounds__(256) void softmax_kernel(float* __restrict__ S)
{
    const float scale = 0.03125f;  // 1/sqrt(1024)
    float* row = S + (size_t)blockIdx.x * SEQ;
    const int t = threadIdx.x;

    __shared__ float smax[8];
    __shared__ float ssum[8];

    float4 v[4];
    float m = -1e30f;
#pragma unroll
    for (int i = 0; i < 4; i++) {
        v[i] = *reinterpret_cast<float4*>(&row[t * 16 + i * 4]);
        v[i].x *= scale; v[i].y *= scale; v[i].z *= scale; v[i].w *= scale;
        m = fmaxf(m, fmaxf(fmaxf(v[i].x, v[i].y), fmaxf(v[i].z, v[i].w)));
    }
#pragma unroll
    for (int o = 16; o > 0; o >>= 1) m = fmaxf(m, __shfl_xor_sync(0xffffffffu, m, o));
    if ((t & 31) == 0) smax[t >> 5] = m;
    __syncthreads();
    m = smax[0];
#pragma unroll
    for (int w = 1; w < 8; w++) m = fmaxf(m, smax[w]);

    float s = 0.0f;
#pragma unroll
    for (int i = 0; i < 4; i++) {
        v[i].x = expf(v[i].x - m);
        v[i].y = expf(v[i].y - m);
        v[i].z = expf(v[i].z - m);
        v[i].w = expf(v[i].w - m);
        s += v[i].x + v[i].y + v[i].z + v[i].w;
    }
#pragma unroll
    for (int o = 16; o > 0; o >>= 1) s += __shfl_xor_sync(0xffffffffu, s, o);
    if ((t & 31) == 0) ssum[t >> 5] = s;
    __syncthreads();
    s = ssum[0];
#pragma unroll
    for (int w = 1; w < 8; w++) s += ssum[w];
    const float inv = 1.0f / s;

#pragma unroll
    for (int i = 0; i < 4; i++) {
        v[i].x *= inv; v[i].y *= inv; v[i].z *= inv; v[i].w *= inv;
        *reinterpret_cast<float4*>(&row[t * 16 + i * 4]) = v[i];
    }
}

// ---------------------------------------------------------------------------
extern "C" void kernel_launch(void* const* d_in, const int* in_sizes, int n_in,
                              void* d_out, int out_size)
{
    const float* x  = (const float*)d_in[0];
    const float* wq = (const float*)d_in[1];
    const float* wk = (const float*)d_in[2];
    const float* wv = (const float*)d_in[3];
    float* out = (float*)d_out;

    float *Q, *K, *V, *S;
    cudaGetSymbolAddress((void**)&Q, g_Q);
    cudaGetSymbolAddress((void**)&K, g_K);
    cudaGetSymbolAddress((void**)&V, g_V);
    cudaGetSymbolAddress((void**)&S, g_S);

    dim3 block(256);
    dim3 grid_proj(DMODEL / 128, SEQ / 128);   // (8, 32)
    dim3 grid_qk(SEQ / 128, SEQ / 128);        // (32, 32)
    dim3 grid_pv(DMODEL / 128, SEQ / 128);     // (8, 32)

    // Projections: [4096,1024] @ [1024,1024]
    sgemm_kernel<false><<<grid_proj, block>>>(x, wq, Q, SEQ, DMODEL, DMODEL);
    sgemm_kernel<false><<<grid_proj, block>>>(x, wk, K, SEQ, DMODEL, DMODEL);
    sgemm_kernel<false><<<grid_proj, block>>>(x, wv, V, SEQ, DMODEL, DMODEL);

    // Scores: S = Q @ K^T  [4096,4096]
    sgemm_kernel<true><<<grid_qk, block>>>(Q, K, S, SEQ, SEQ, DMODEL);

    // Softmax(S / 32) row-wise, in place
    softmax_kernel<<<SEQ, block>>>(S);

    // Context: out = P @ V  [4096,1024]
    sgemm_kernel<false><<<grid_pv, block>>>(S, V, out, SEQ, DMODEL, SEQ);
}

// round 3
// speedup vs baseline: 1.5206x; 1.5206x over previous
#include <cuda_runtime.h>
#include <cuda_bf16.h>
#include <cstdint>
#include <cstddef>

#define SEQ 4096
#define DMODEL 1024

// ---------------------------------------------------------------------------
// Scratch (allocation-free rule: device globals)
// ---------------------------------------------------------------------------
__device__ __align__(128) float g_Q[(size_t)SEQ * DMODEL];
__device__ __align__(128) float g_K[(size_t)SEQ * DMODEL];
__device__ __align__(128) float g_V[(size_t)SEQ * DMODEL];
__device__ __align__(128) float g_S[(size_t)SEQ * SEQ];

__device__ __align__(128) __nv_bfloat16 g_Xh[(size_t)SEQ * DMODEL];
__device__ __align__(128) __nv_bfloat16 g_Xl[(size_t)SEQ * DMODEL];
__device__ __align__(128) __nv_bfloat16 g_Wqh[(size_t)DMODEL * DMODEL];
__device__ __align__(128) __nv_bfloat16 g_Wql[(size_t)DMODEL * DMODEL];
__device__ __align__(128) __nv_bfloat16 g_Wkh[(size_t)DMODEL * DMODEL];
__device__ __align__(128) __nv_bfloat16 g_Wkl[(size_t)DMODEL * DMODEL];
__device__ __align__(128) __nv_bfloat16 g_Wvh[(size_t)DMODEL * DMODEL];
__device__ __align__(128) __nv_bfloat16 g_Wvl[(size_t)DMODEL * DMODEL];
__device__ __align__(128) __nv_bfloat16 g_Qh[(size_t)SEQ * DMODEL];
__device__ __align__(128) __nv_bfloat16 g_Ql[(size_t)SEQ * DMODEL];
__device__ __align__(128) __nv_bfloat16 g_Kh[(size_t)SEQ * DMODEL];
__device__ __align__(128) __nv_bfloat16 g_Kl[(size_t)SEQ * DMODEL];
__device__ __align__(128) __nv_bfloat16 g_Vth[(size_t)DMODEL * SEQ];
__device__ __align__(128) __nv_bfloat16 g_Vtl[(size_t)DMODEL * SEQ];
__device__ __align__(128) __nv_bfloat16 g_Ph[(size_t)SEQ * SEQ];
__device__ __align__(128) __nv_bfloat16 g_Pl[(size_t)SEQ * SEQ];

// ---------------------------------------------------------------------------
// PTX helpers (all base-PTX features: sm_80/sm_90 era, no "a" suffix needed)
// ---------------------------------------------------------------------------
__device__ __forceinline__ uint32_t smem_u32(const void* p) {
    uint32_t a;
    asm("{ .reg .u64 t; cvta.to.shared.u64 t, %1; cvt.u32.u64 %0, t; }"
        : "=r"(a) : "l"(p));
    return a;
}
#define CP_ASYNC16(dst, src) \
    asm volatile("cp.async.cg.shared.global [%0], [%1], 16;" \
                 :: "r"(dst), "l"(src) : "memory")
#define CP_COMMIT() asm volatile("cp.async.commit_group;" ::: "memory")
#define CP_WAIT2()  asm volatile("cp.async.wait_group 2;" ::: "memory")

#define LDSM_X4(r0, r1, r2, r3, addr) \
    asm volatile("ldmatrix.sync.aligned.m8n8.x4.shared.b16 {%0,%1,%2,%3}, [%4];" \
                 : "=r"(r0), "=r"(r1), "=r"(r2), "=r"(r3) : "r"(addr))

#define MMA_BF16(d, a, b) \
    asm volatile("mma.sync.aligned.m16n8k16.row.col.f32.bf16.bf16.f32 " \
                 "{%0,%1,%2,%3}, {%4,%5,%6,%7}, {%8,%9}, {%0,%1,%2,%3};" \
                 : "+f"((d)[0]), "+f"((d)[1]), "+f"((d)[2]), "+f"((d)[3]) \
                 : "r"((a)[0]), "r"((a)[1]), "r"((a)[2]), "r"((a)[3]), \
                   "r"((b)[0]), "r"((b)[1]))

// ---------------------------------------------------------------------------
// HMMA GEMM:  C[M, Nglob] = (Ah+Al)[M, Kd] @ (Bh+Bl)[Nglob, Kd]^T
// bf16 split, fp32 accum; 3 MMA passes (hh, hl, lh).
// CTA tile 128x128x64, 8 warps (4x2), warp tile 32x64.
// 3-stage cp.async pipeline; SW128-XOR smem layout (conflict-free LDSM/STS).
// ---------------------------------------------------------------------------
#define BK 64
#define TILE_B   16384          // one 128x64 bf16 tile
#define STAGE_B  (4 * TILE_B)   // Ah | Al | Bh | Bl
#define NSTAGE   3
#define GEMM_SMEM (NSTAGE * STAGE_B)   // 196608

__device__ __forceinline__ uint32_t sw_off(int row, int chunk) {
    uint32_t off = (uint32_t)(row * 128 + chunk * 16);
    return off ^ ((off >> 3) & 0x70);
}

__global__ __launch_bounds__(256, 1) void hmma_gemm_nt(
    const __nv_bfloat16* __restrict__ Ah, const __nv_bfloat16* __restrict__ Al,
    const __nv_bfloat16* __restrict__ Bh, const __nv_bfloat16* __restrict__ Bl,
    float* __restrict__ C, int Kd, int Nglob)
{
    extern __shared__ char smem[];
    const int tid = threadIdx.x;
    const int wid = tid >> 5;
    const int lane = tid & 31;
    const int warp_m = wid >> 1;          // 0..3 -> M offset 32*warp_m
    const int warp_n = wid & 1;           // 0..1 -> N offset 64*warp_n
    const int bx = blockIdx.x, by = blockIdx.y;

    const size_t a_row0 = (size_t)by * 128;
    const size_t b_row0 = (size_t)bx * 128;
    const int NKT = Kd / BK;

    // per-thread load slots: f = tid + it*256 ; r = f>>3, c8 = f&7
    const int ld_r  = tid >> 3;          // 0..31 (+32 per it)
    const int ld_c8 = tid & 7;
    const uint32_t ld_sw = sw_off(ld_r, ld_c8);

    auto load_tile = [&](int s, int kt) {
        char* base = smem + s * STAGE_B;
        const size_t kcol = (size_t)kt * BK + ld_c8 * 8;
#pragma unroll
        for (int v = 0; v < 4; v++) {
            const __nv_bfloat16* src =
                (v == 0) ? Ah : (v == 1) ? Al : (v == 2) ? Bh : Bl;
            const size_t row0 = (v < 2) ? a_row0 : b_row0;
            uint32_t dst0 = smem_u32(base + v * TILE_B) + ld_sw;
#pragma unroll
            for (int it = 0; it < 4; it++) {
                const __nv_bfloat16* gsrc =
                    src + (row0 + ld_r + it * 32) * Kd + kcol;
                // row advances by 32 -> sw XOR bits unchanged (row&7 same)
                CP_ASYNC16(dst0 + it * 32 * 128, gsrc);
            }
        }
    };

    // Prologue: fill 3 stages
#pragma unroll
    for (int s = 0; s < NSTAGE; s++) { load_tile(s, s); CP_COMMIT(); }

    float acc[2][8][4];
#pragma unroll
    for (int mt = 0; mt < 2; mt++)
#pragma unroll
        for (int nt = 0; nt < 8; nt++)
#pragma unroll
            for (int c = 0; c < 4; c++) acc[mt][nt][c] = 0.0f;

    // ldmatrix lane addressing
    const int lm_row = lane & 15;
    const int lm_hi  = lane >> 4;

#pragma unroll 1
    for (int kt = 0; kt < NKT; kt++) {
        CP_WAIT2();
        __syncthreads();
        char* buf = smem + (kt % NSTAGE) * STAGE_B;
        const uint32_t sAh = smem_u32(buf);
        const uint32_t sAl = sAh + TILE_B;
        const uint32_t sBh = sAh + 2 * TILE_B;
        const uint32_t sBl = sAh + 3 * TILE_B;

#pragma unroll
        for (int ks = 0; ks < 4; ks++) {
            const int chunk = ks * 2 + lm_hi;
            uint32_t a_h[2][4], a_l[2][4], b_h[8][2], b_l[8][2];
#pragma unroll
            for (int mt = 0; mt < 2; mt++) {
                const int row = warp_m * 32 + mt * 16 + lm_row;
                const uint32_t so = sw_off(row, chunk);
                LDSM_X4(a_h[mt][0], a_h[mt][1], a_h[mt][2], a_h[mt][3], sAh + so);
                LDSM_X4(a_l[mt][0], a_l[mt][1], a_l[mt][2], a_l[mt][3], sAl + so);
            }
#pragma unroll
            for (int np = 0; np < 4; np++) {
                const int row = warp_n * 64 + np * 16 + lm_row;
                const uint32_t so = sw_off(row, chunk);
                uint32_t t0, t1, t2, t3;
                LDSM_X4(t0, t1, t2, t3, sBh + so);
                b_h[2 * np][0] = t0; b_h[2 * np][1] = t2;
                b_h[2 * np + 1][0] = t1; b_h[2 * np + 1][1] = t3;
                LDSM_X4(t0, t1, t2, t3, sBl + so);
                b_l[2 * np][0] = t0; b_l[2 * np][1] = t2;
                b_l[2 * np + 1][0] = t1; b_l[2 * np + 1][1] = t3;
            }
#pragma unroll
            for (int mt = 0; mt < 2; mt++)
#pragma unroll
                for (int nt = 0; nt < 8; nt++) {
                    MMA_BF16(acc[mt][nt], a_h[mt], b_h[nt]);
                    MMA_BF16(acc[mt][nt], a_h[mt], b_l[nt]);
                    MMA_BF16(acc[mt][nt], a_l[mt], b_h[nt]);
                }
        }
        __syncthreads();
        if (kt + NSTAGE < NKT) load_tile(kt % NSTAGE, kt + NSTAGE);
        CP_COMMIT();
    }

    // Epilogue: registers -> C directly (float2 stores)
    const int g = lane >> 2;
    const int t2 = (lane & 3) * 2;
#pragma unroll
    for (int mt = 0; mt < 2; mt++) {
        const size_t r0 = a_row0 + warp_m * 32 + mt * 16 + g;
#pragma unroll
        for (int nt = 0; nt < 8; nt++) {
            const size_t col = b_row0 + warp_n * 64 + nt * 8 + t2;
            float2 v0 = make_float2(acc[mt][nt][0], acc[mt][nt][1]);
            float2 v1 = make_float2(acc[mt][nt][2], acc[mt][nt][3]);
            *reinterpret_cast<float2*>(&C[r0 * Nglob + col]) = v0;
            *reinterpret_cast<float2*>(&C[(r0 + 8) * Nglob + col]) = v1;
        }
    }
}

// ---------------------------------------------------------------------------
// f32 -> (hi, lo) bf16 split, elementwise
// ---------------------------------------------------------------------------
__device__ __forceinline__ void split1(float x, __nv_bfloat16& h, __nv_bfloat16& l) {
    h = __float2bfloat16(x);
    l = __float2bfloat16(x - __bfloat162float(h));
}

__global__ __launch_bounds__(256) void split_kernel(
    const float* __restrict__ in, __nv_bfloat16* __restrict__ hi,
    __nv_bfloat16* __restrict__ lo, int n4)
{
    int i = blockIdx.x * blockDim.x + threadIdx.x;
    if (i >= n4) return;
    float4 v = reinterpret_cast<const float4*>(in)[i];
    __nv_bfloat16 h0, h1, h2, h3, l0, l1, l2, l3;
    split1(v.x, h0, l0); split1(v.y, h1, l1);
    split1(v.z, h2, l2); split1(v.w, h3, l3);
    __nv_bfloat162* ph = reinterpret_cast<__nv_bfloat162*>(hi);
    __nv_bfloat162* pl = reinterpret_cast<__nv_bfloat162*>(lo);
    ph[2 * i + 0] = __halves2bfloat162(h0, h1);
    ph[2 * i + 1] = __halves2bfloat162(h2, h3);
    pl[2 * i + 0] = __halves2bfloat162(l0, l1);
    pl[2 * i + 1] = __halves2bfloat162(l2, l3);
}

// ---------------------------------------------------------------------------
// transpose + split: in f32 [R, C] -> out hi/lo bf16 [C, R]
// ---------------------------------------------------------------------------
__global__ __launch_bounds__(256) void transpose_split_kernel(
    const float* __restrict__ in, __nv_bfloat16* __restrict__ oh,
    __nv_bfloat16* __restrict__ ol, int R, int C)
{
    __shared__ float t[32][33];
    const int bx = blockIdx.x * 32;   // over C
    const int by = blockIdx.y * 32;   // over R
    const int tx = threadIdx.x, ty = threadIdx.y;   // 32 x 8
#pragma unroll
    for (int j = 0; j < 4; j++)
        t[ty + 8 * j][tx] = in[(size_t)(by + ty + 8 * j) * C + bx + tx];
    __syncthreads();
#pragma unroll
    for (int j = 0; j < 4; j++) {
        float v = t[tx][ty + 8 * j];
        __nv_bfloat16 h, l;
        split1(v, h, l);
        size_t o = (size_t)(bx + ty + 8 * j) * R + by + tx;
        oh[o] = h;
        ol[o] = l;
    }
}

// ---------------------------------------------------------------------------
// Fused scale + softmax over rows of S [SEQ, SEQ]; writes split bf16 P.
// ---------------------------------------------------------------------------
__global__ __launch_bounds__(256) void softmax_split_kernel(
    const float* __restrict__ S, __nv_bfloat16* __restrict__ Ph,
    __nv_bfloat16* __restrict__ Pl)
{
    const float scale = 0.03125f;   // 1/sqrt(1024)
    const float* row = S + (size_t)blockIdx.x * SEQ;
    const int t = threadIdx.x;

    __shared__ float smax[8];
    __shared__ float ssum[8];

    float4 v[4];
    float m = -1e30f;
#pragma unroll
    for (int i = 0; i < 4; i++) {
        v[i] = *reinterpret_cast<const float4*>(&row[t * 16 + i * 4]);
        v[i].x *= scale; v[i].y *= scale; v[i].z *= scale; v[i].w *= scale;
        m = fmaxf(m, fmaxf(fmaxf(v[i].x, v[i].y), fmaxf(v[i].z, v[i].w)));
    }
#pragma unroll
    for (int o = 16; o > 0; o >>= 1) m = fmaxf(m, __shfl_xor_sync(0xffffffffu, m, o));
    if ((t & 31) == 0) smax[t >> 5] = m;
    __syncthreads();
    m = smax[0];
#pragma unroll
    for (int w = 1; w < 8; w++) m = fmaxf(m, smax[w]);

    float s = 0.0f;
#pragma unroll
    for (int i = 0; i < 4; i++) {
        v[i].x = expf(v[i].x - m); v[i].y = expf(v[i].y - m);
        v[i].z = expf(v[i].z - m); v[i].w = expf(v[i].w - m);
        s += v[i].x + v[i].y + v[i].z + v[i].w;
    }
#pragma unroll
    for (int o = 16; o > 0; o >>= 1) s += __shfl_xor_sync(0xffffffffu, s, o);
    if ((t & 31) == 0) ssum[t >> 5] = s;
    __syncthreads();
    s = ssum[0];
#pragma unroll
    for (int w = 1; w < 8; w++) s += ssum[w];
    const float inv = 1.0f / s;

    __nv_bfloat162* ph = reinterpret_cast<__nv_bfloat162*>(
        Ph + (size_t)blockIdx.x * SEQ);
    __nv_bfloat162* pl = reinterpret_cast<__nv_bfloat162*>(
        Pl + (size_t)blockIdx.x * SEQ);
#pragma unroll
    for (int i = 0; i < 4; i++) {
        float f0 = v[i].x * inv, f1 = v[i].y * inv;
        float f2 = v[i].z * inv, f3 = v[i].w * inv;
        __nv_bfloat16 h0, h1, h2, h3, l0, l1, l2, l3;
        split1(f0, h0, l0); split1(f1, h1, l1);
        split1(f2, h2, l2); split1(f3, h3, l3);
        int idx = (t * 16 + i * 4) >> 1;
        ph[idx + 0] = __halves2bfloat162(h0, h1);
        ph[idx + 1] = __halves2bfloat162(h2, h3);
        pl[idx + 0] = __halves2bfloat162(l0, l1);
        pl[idx + 1] = __halves2bfloat162(l2, l3);
    }
}

// ---------------------------------------------------------------------------
extern "C" void kernel_launch(void* const* d_in, const int* in_sizes, int n_in,
                              void* d_out, int out_size)
{
    const float* x  = (const float*)d_in[0];
    const float* wq = (const float*)d_in[1];
    const float* wk = (const float*)d_in[2];
    const float* wv = (const float*)d_in[3];
    float* out = (float*)d_out;

    float *Q, *K, *V, *S;
    __nv_bfloat16 *Xh, *Xl, *Wqh, *Wql, *Wkh, *Wkl, *Wvh, *Wvl;
    __nv_bfloat16 *Qh, *Ql, *Kh, *Kl, *Vth, *Vtl, *Ph, *Pl;
    cudaGetSymbolAddress((void**)&Q, g_Q);
    cudaGetSymbolAddress((void**)&K, g_K);
    cudaGetSymbolAddress((void**)&V, g_V);
    cudaGetSymbolAddress((void**)&S, g_S);
    cudaGetSymbolAddress((void**)&Xh, g_Xh);   cudaGetSymbolAddress((void**)&Xl, g_Xl);
    cudaGetSymbolAddress((void**)&Wqh, g_Wqh); cudaGetSymbolAddress((void**)&Wql, g_Wql);
    cudaGetSymbolAddress((void**)&Wkh, g_Wkh); cudaGetSymbolAddress((void**)&Wkl, g_Wkl);
    cudaGetSymbolAddress((void**)&Wvh, g_Wvh); cudaGetSymbolAddress((void**)&Wvl, g_Wvl);
    cudaGetSymbolAddress((void**)&Qh, g_Qh);   cudaGetSymbolAddress((void**)&Ql, g_Ql);
    cudaGetSymbolAddress((void**)&Kh, g_Kh);   cudaGetSymbolAddress((void**)&Kl, g_Kl);
    cudaGetSymbolAddress((void**)&Vth, g_Vth); cudaGetSymbolAddress((void**)&Vtl, g_Vtl);
    cudaGetSymbolAddress((void**)&Ph, g_Ph);   cudaGetSymbolAddress((void**)&Pl, g_Pl);

    cudaFuncSetAttribute(hmma_gemm_nt,
                         cudaFuncAttributeMaxDynamicSharedMemorySize, GEMM_SMEM);

    const int nXd4 = SEQ * DMODEL / 4;

    // 1. Split X; transpose+split weights.
    split_kernel<<<(nXd4 + 255) / 256, 256>>>(x, Xh, Xl, nXd4);
    dim3 tb(32, 8);
    transpose_split_kernel<<<dim3(DMODEL / 32, DMODEL / 32), tb>>>(wq, Wqh, Wql, DMODEL, DMODEL);
    transpose_split_kernel<<<dim3(DMODEL / 32, DMODEL / 32), tb>>>(wk, Wkh, Wkl, DMODEL, DMODEL);
    transpose_split_kernel<<<dim3(DMODEL / 32, DMODEL / 32), tb>>>(wv, Wvh, Wvl, DMODEL, DMODEL);

    // 2. Projections: Q/K/V = X @ W  (B given as W^T [N,K])
    dim3 gp(DMODEL / 128, SEQ / 128);   // (8, 32)
    hmma_gemm_nt<<<gp, 256, GEMM_SMEM>>>(Xh, Xl, Wqh, Wql, Q, DMODEL, DMODEL);
    hmma_gemm_nt<<<gp, 256, GEMM_SMEM>>>(Xh, Xl, Wkh, Wkl, K, DMODEL, DMODEL);
    hmma_gemm_nt<<<gp, 256, GEMM_SMEM>>>(Xh, Xl, Wvh, Wvl, V, DMODEL, DMODEL);

    // 3. Split Q and K; transpose+split V.
    split_kernel<<<(nXd4 + 255) / 256, 256>>>(Q, Qh, Ql, nXd4);
    split_kernel<<<(nXd4 + 255) / 256, 256>>>(K, Kh, Kl, nXd4);
    transpose_split_kernel<<<dim3(DMODEL / 32, SEQ / 32), tb>>>(V, Vth, Vtl, SEQ, DMODEL);

    // 4. Scores: S = Q @ K^T
    dim3 gs(SEQ / 128, SEQ / 128);      // (32, 32)
    hmma_gemm_nt<<<gs, 256, GEMM_SMEM>>>(Qh, Ql, Kh, Kl, S, DMODEL, SEQ);

    // 5. Softmax(S/32) -> split P
    softmax_split_kernel<<<SEQ, 256>>>(S, Ph, Pl);

    // 6. Context: out = P @ V   (B = V^T [DMODEL, SEQ])
    dim3 gc(DMODEL / 128, SEQ / 128);   // (8, 32)
    hmma_gemm_nt<<<gc, 256, GEMM_SMEM>>>(Ph, Pl, Vth, Vtl, out, SEQ, DMODEL);
}

// round 5
// speedup vs baseline: 2.3159x; 1.5230x over previous
#include <cuda_runtime.h>
#include <cuda_bf16.h>
#include <cstdint>
#include <cstddef>

#define SEQ 4096
#define DMODEL 1024

// ---------------------------------------------------------------------------
// Scratch (allocation-free rule: device globals)
// ---------------------------------------------------------------------------
__device__ __align__(128) float g_Q[(size_t)SEQ * DMODEL];
__device__ __align__(128) float g_K[(size_t)SEQ * DMODEL];
__device__ __align__(128) float g_V[(size_t)SEQ * DMODEL];
__device__ __align__(128) float g_S[(size_t)SEQ * SEQ];

__device__ __align__(128) __nv_bfloat16 g_Xh[(size_t)SEQ * DMODEL];
__device__ __align__(128) __nv_bfloat16 g_Xl[(size_t)SEQ * DMODEL];
__device__ __align__(128) __nv_bfloat16 g_Wqh[(size_t)DMODEL * DMODEL];
__device__ __align__(128) __nv_bfloat16 g_Wql[(size_t)DMODEL * DMODEL];
__device__ __align__(128) __nv_bfloat16 g_Wkh[(size_t)DMODEL * DMODEL];
__device__ __align__(128) __nv_bfloat16 g_Wkl[(size_t)DMODEL * DMODEL];
__device__ __align__(128) __nv_bfloat16 g_Wvh[(size_t)DMODEL * DMODEL];
__device__ __align__(128) __nv_bfloat16 g_Wvl[(size_t)DMODEL * DMODEL];
__device__ __align__(128) __nv_bfloat16 g_Qh[(size_t)SEQ * DMODEL];
__device__ __align__(128) __nv_bfloat16 g_Ql[(size_t)SEQ * DMODEL];
__device__ __align__(128) __nv_bfloat16 g_Kh[(size_t)SEQ * DMODEL];
__device__ __align__(128) __nv_bfloat16 g_Kl[(size_t)SEQ * DMODEL];
__device__ __align__(128) __nv_bfloat16 g_Vth[(size_t)DMODEL * SEQ];
__device__ __align__(128) __nv_bfloat16 g_Vtl[(size_t)DMODEL * SEQ];
__device__ __align__(128) __nv_bfloat16 g_Ph[(size_t)SEQ * SEQ];
__device__ __align__(128) __nv_bfloat16 g_Pl[(size_t)SEQ * SEQ];

// ---------------------------------------------------------------------------
// PTX helpers (base PTX only; no sm_103a-suffix features usable here)
// ---------------------------------------------------------------------------
__device__ __forceinline__ uint32_t smem_u32(const void* p) {
    uint32_t a;
    asm("{ .reg .u64 t; cvta.to.shared.u64 t, %1; cvt.u32.u64 %0, t; }"
        : "=r"(a) : "l"(p));
    return a;
}
#define CP_ASYNC16(dst, src) \
    asm volatile("cp.async.cg.shared.global [%0], [%1], 16;" \
                 :: "r"(dst), "l"(src) : "memory")
#define CP_COMMIT() asm volatile("cp.async.commit_group;" ::: "memory")
#define CP_WAIT1()  asm volatile("cp.async.wait_group 1;" ::: "memory")

#define LDSM_X4(r0, r1, r2, r3, addr) \
    asm volatile("ldmatrix.sync.aligned.m8n8.x4.shared.b16 {%0,%1,%2,%3}, [%4];" \
                 : "=r"(r0), "=r"(r1), "=r"(r2), "=r"(r3) : "r"(addr))

#define MMA_BF16(d, a, b) \
    asm volatile("mma.sync.aligned.m16n8k16.row.col.f32.bf16.bf16.f32 " \
                 "{%0,%1,%2,%3}, {%4,%5,%6,%7}, {%8,%9}, {%0,%1,%2,%3};" \
                 : "+f"((d)[0]), "+f"((d)[1]), "+f"((d)[2]), "+f"((d)[3]) \
                 : "r"((a)[0]), "r"((a)[1]), "r"((a)[2]), "r"((a)[3]), \
                   "r"((b)[0]), "r"((b)[1]))

// ---------------------------------------------------------------------------
// HMMA GEMM:  C[M, Nglob] = (Ah+Al)[M, Kd] @ (Bh+Bl)[Nglob, Kd]^T
// bf16 split, fp32 accum; 3 MMA passes (hh, hl, lh).
// CTA tile 128x256x64, 8 warps (2x4), warp tile 64x64.
// 2-stage cp.async pipeline; SW128-XOR smem layout.
// ---------------------------------------------------------------------------
#define BK 64
#define A_TILE_B 16384          // 128 x 64 bf16
#define B_TILE_B 32768          // 256 x 64 bf16
#define STAGE_B  (2 * A_TILE_B + 2 * B_TILE_B)   // Ah|Al|Bh|Bl = 96KB
#define NSTAGE   2
#define GEMM_SMEM (NSTAGE * STAGE_B)             // 196608

__device__ __forceinline__ uint32_t sw_off(int row, int chunk) {
    uint32_t off = (uint32_t)(row * 128 + chunk * 16);
    return off ^ ((off >> 3) & 0x70);
}

__global__ __launch_bounds__(256, 1) void hmma_gemm_nt(
    const __nv_bfloat16* __restrict__ Ah, const __nv_bfloat16* __restrict__ Al,
    const __nv_bfloat16* __restrict__ Bh, const __nv_bfloat16* __restrict__ Bl,
    float* __restrict__ C, int Kd, int Nglob)
{
    extern __shared__ char smem[];
    const int tid = threadIdx.x;
    const int wid = tid >> 5;
    const int lane = tid & 31;
    const int warp_m = wid >> 2;          // 0..1 -> M offset 64*warp_m
    const int warp_n = wid & 3;           // 0..3 -> N offset 64*warp_n
    const int bx = blockIdx.x, by = blockIdx.y;

    const size_t a_row0 = (size_t)by * 128;
    const size_t b_row0 = (size_t)bx * 256;
    const int NKT = Kd / BK;

    // cp.async per-thread slots: r = tid>>3 (+32/iter), c8 = tid&7
    const int ld_r  = tid >> 3;
    const int ld_c8 = tid & 7;
    const uint32_t ld_sw = sw_off(ld_r, ld_c8);

    auto load_tile = [&](int s, int kt) {
        char* base = smem + s * STAGE_B;
        const size_t kcol = (size_t)kt * BK + ld_c8 * 8;
        // A hi/lo: 128 rows -> 4 iters each
#pragma unroll
        for (int v = 0; v < 2; v++) {
            const __nv_bfloat16* src = v ? Al : Ah;
            uint32_t dst0 = smem_u32(base + v * A_TILE_B) + ld_sw;
#pragma unroll
            for (int it = 0; it < 4; it++)
                CP_ASYNC16(dst0 + it * 32 * 128,
                           src + (a_row0 + ld_r + it * 32) * Kd + kcol);
        }
        // B hi/lo: 256 rows -> 8 iters each
#pragma unroll
        for (int v = 0; v < 2; v++) {
            const __nv_bfloat16* src = v ? Bl : Bh;
            uint32_t dst0 = smem_u32(base + 2 * A_TILE_B + v * B_TILE_B) + ld_sw;
#pragma unroll
            for (int it = 0; it < 8; it++)
                CP_ASYNC16(dst0 + it * 32 * 128,
                           src + (b_row0 + ld_r + it * 32) * Kd + kcol);
        }
    };

    load_tile(0, 0); CP_COMMIT();
    load_tile(1, 1); CP_COMMIT();

    float acc[4][8][4];
#pragma unroll
    for (int mt = 0; mt < 4; mt++)
#pragma unroll
        for (int nt = 0; nt < 8; nt++)
#pragma unroll
            for (int c = 0; c < 4; c++) acc[mt][nt][c] = 0.0f;

    const int lm_row = lane & 15;
    const int lm_hi  = lane >> 4;

#pragma unroll 1
    for (int kt = 0; kt < NKT; kt++) {
        CP_WAIT1();
        __syncthreads();
        char* buf = smem + (kt & 1) * STAGE_B;
        const uint32_t sAh = smem_u32(buf);
        const uint32_t sAl = sAh + A_TILE_B;
        const uint32_t sBh = sAh + 2 * A_TILE_B;
        const uint32_t sBl = sBh + B_TILE_B;

#pragma unroll
        for (int ks = 0; ks < 4; ks++) {
            const int chunk = ks * 2 + lm_hi;
            uint32_t a_h[4][4], a_l[4][4];
#pragma unroll
            for (int mt = 0; mt < 4; mt++) {
                const int row = warp_m * 64 + mt * 16 + lm_row;
                const uint32_t so = sw_off(row, chunk);
                LDSM_X4(a_h[mt][0], a_h[mt][1], a_h[mt][2], a_h[mt][3], sAh + so);
                LDSM_X4(a_l[mt][0], a_l[mt][1], a_l[mt][2], a_l[mt][3], sAl + so);
            }
#pragma unroll
            for (int half = 0; half < 2; half++) {
                uint32_t b_h[4][2], b_l[4][2];
#pragma unroll
                for (int np = 0; np < 2; np++) {
                    const int row = warp_n * 64 + half * 32 + np * 16 + lm_row;
                    const uint32_t so = sw_off(row, chunk);
                    uint32_t t0, t1, t2, t3;
                    LDSM_X4(t0, t1, t2, t3, sBh + so);
                    b_h[2 * np][0] = t0;     b_h[2 * np][1] = t2;
                    b_h[2 * np + 1][0] = t1; b_h[2 * np + 1][1] = t3;
                    LDSM_X4(t0, t1, t2, t3, sBl + so);
                    b_l[2 * np][0] = t0;     b_l[2 * np][1] = t2;
                    b_l[2 * np + 1][0] = t1; b_l[2 * np + 1][1] = t3;
                }
#pragma unroll
                for (int mt = 0; mt < 4; mt++)
#pragma unroll
                    for (int nb = 0; nb < 4; nb++) {
                        float* d = acc[mt][half * 4 + nb];
                        MMA_BF16(d, a_h[mt], b_h[nb]);
                        MMA_BF16(d, a_h[mt], b_l[nb]);
                        MMA_BF16(d, a_l[mt], b_h[nb]);
                    }
            }
        }
        __syncthreads();
        if (kt + NSTAGE < NKT) load_tile(kt & 1, kt + NSTAGE);
        CP_COMMIT();
    }

    // Epilogue: registers -> C (float2 stores)
    const int g = lane >> 2;
    const int t2 = (lane & 3) * 2;
#pragma unroll
    for (int mt = 0; mt < 4; mt++) {
        const size_t r0 = a_row0 + warp_m * 64 + mt * 16 + g;
#pragma unroll
        for (int nt = 0; nt < 8; nt++) {
            const size_t col = b_row0 + warp_n * 64 + nt * 8 + t2;
            *reinterpret_cast<float2*>(&C[r0 * Nglob + col]) =
                make_float2(acc[mt][nt][0], acc[mt][nt][1]);
            *reinterpret_cast<float2*>(&C[(r0 + 8) * Nglob + col]) =
                make_float2(acc[mt][nt][2], acc[mt][nt][3]);
        }
    }
}

// ---------------------------------------------------------------------------
// f32 -> (hi, lo) bf16 split, elementwise
// ---------------------------------------------------------------------------
__device__ __forceinline__ void split1(float x, __nv_bfloat16& h, __nv_bfloat16& l) {
    h = __float2bfloat16(x);
    l = __float2bfloat16(x - __bfloat162float(h));
}

__global__ __launch_bounds__(256) void split_kernel(
    const float* __restrict__ in, __nv_bfloat16* __restrict__ hi,
    __nv_bfloat16* __restrict__ lo, int n4)
{
    int i = blockIdx.x * blockDim.x + threadIdx.x;
    if (i >= n4) return;
    float4 v = reinterpret_cast<const float4*>(in)[i];
    __nv_bfloat16 h0, h1, h2, h3, l0, l1, l2, l3;
    split1(v.x, h0, l0); split1(v.y, h1, l1);
    split1(v.z, h2, l2); split1(v.w, h3, l3);
    __nv_bfloat162* ph = reinterpret_cast<__nv_bfloat162*>(hi);
    __nv_bfloat162* pl = reinterpret_cast<__nv_bfloat162*>(lo);
    ph[2 * i + 0] = __halves2bfloat162(h0, h1);
    ph[2 * i + 1] = __halves2bfloat162(h2, h3);
    pl[2 * i + 0] = __halves2bfloat162(l0, l1);
    pl[2 * i + 1] = __halves2bfloat162(l2, l3);
}

// ---------------------------------------------------------------------------
// transpose + split: in f32 [R, C] -> out hi/lo bf16 [C, R]
// ---------------------------------------------------------------------------
__global__ __launch_bounds__(256) void transpose_split_kernel(
    const float* __restrict__ in, __nv_bfloat16* __restrict__ oh,
    __nv_bfloat16* __restrict__ ol, int R, int C)
{
    __shared__ float t[32][33];
    const int bx = blockIdx.x * 32;
    const int by = blockIdx.y * 32;
    const int tx = threadIdx.x, ty = threadIdx.y;   // 32 x 8
#pragma unroll
    for (int j = 0; j < 4; j++)
        t[ty + 8 * j][tx] = in[(size_t)(by + ty + 8 * j) * C + bx + tx];
    __syncthreads();
#pragma unroll
    for (int j = 0; j < 4; j++) {
        float v = t[tx][ty + 8 * j];
        __nv_bfloat16 h, l;
        split1(v, h, l);
        size_t o = (size_t)(bx + ty + 8 * j) * R + by + tx;
        oh[o] = h;
        ol[o] = l;
    }
}

// ---------------------------------------------------------------------------
// Fused scale + softmax over rows of S [SEQ, SEQ]; writes split bf16 P.
// ---------------------------------------------------------------------------
__global__ __launch_bounds__(256) void softmax_split_kernel(
    const float* __restrict__ S, __nv_bfloat16* __restrict__ Ph,
    __nv_bfloat16* __restrict__ Pl)
{
    const float scale = 0.03125f;   // 1/sqrt(1024)
    const float* row = S + (size_t)blockIdx.x * SEQ;
    const int t = threadIdx.x;

    __shared__ float smax[8];
    __shared__ float ssum[8];

    float4 v[4];
    float m = -1e30f;
#pragma unroll
    for (int i = 0; i < 4; i++) {
        v[i] = *reinterpret_cast<const float4*>(&row[t * 16 + i * 4]);
        v[i].x *= scale; v[i].y *= scale; v[i].z *= scale; v[i].w *= scale;
        m = fmaxf(m, fmaxf(fmaxf(v[i].x, v[i].y), fmaxf(v[i].z, v[i].w)));
    }
#pragma unroll
    for (int o = 16; o > 0; o >>= 1) m = fmaxf(m, __shfl_xor_sync(0xffffffffu, m, o));
    if ((t & 31) == 0) smax[t >> 5] = m;
    __syncthreads();
    m = smax[0];
#pragma unroll
    for (int w = 1; w < 8; w++) m = fmaxf(m, smax[w]);

    float s = 0.0f;
#pragma unroll
    for (int i = 0; i < 4; i++) {
        v[i].x = __expf(v[i].x - m); v[i].y = __expf(v[i].y - m);
        v[i].z = __expf(v[i].z - m); v[i].w = __expf(v[i].w - m);
        s += v[i].x + v[i].y + v[i].z + v[i].w;
    }
#pragma unroll
    for (int o = 16; o > 0; o >>= 1) s += __shfl_xor_sync(0xffffffffu, s, o);
    if ((t & 31) == 0) ssum[t >> 5] = s;
    __syncthreads();
    s = ssum[0];
#pragma unroll
    for (int w = 1; w < 8; w++) s += ssum[w];
    const float inv = 1.0f / s;

    __nv_bfloat162* ph = reinterpret_cast<__nv_bfloat162*>(
        Ph + (size_t)blockIdx.x * SEQ);
    __nv_bfloat162* pl = reinterpret_cast<__nv_bfloat162*>(
        Pl + (size_t)blockIdx.x * SEQ);
#pragma unroll
    for (int i = 0; i < 4; i++) {
        float f0 = v[i].x * inv, f1 = v[i].y * inv;
        float f2 = v[i].z * inv, f3 = v[i].w * inv;
        __nv_bfloat16 h0, h1, h2, h3, l0, l1, l2, l3;
        split1(f0, h0, l0); split1(f1, h1, l1);
        split1(f2, h2, l2); split1(f3, h3, l3);
        int idx = (t * 16 + i * 4) >> 1;
        ph[idx + 0] = __halves2bfloat162(h0, h1);
        ph[idx + 1] = __halves2bfloat162(h2, h3);
        pl[idx + 0] = __halves2bfloat162(l0, l1);
        pl[idx + 1] = __halves2bfloat162(l2, l3);
    }
}

// ---------------------------------------------------------------------------
extern "C" void kernel_launch(void* const* d_in, const int* in_sizes, int n_in,
                              void* d_out, int out_size)
{
    const float* x  = (const float*)d_in[0];
    const float* wq = (const float*)d_in[1];
    const float* wk = (const float*)d_in[2];
    const float* wv = (const float*)d_in[3];
    float* out = (float*)d_out;

    float *Q, *K, *V, *S;
    __nv_bfloat16 *Xh, *Xl, *Wqh, *Wql, *Wkh, *Wkl, *Wvh, *Wvl;
    __nv_bfloat16 *Qh, *Ql, *Kh, *Kl, *Vth, *Vtl, *Ph, *Pl;
    cudaGetSymbolAddress((void**)&Q, g_Q);
    cudaGetSymbolAddress((void**)&K, g_K);
    cudaGetSymbolAddress((void**)&V, g_V);
    cudaGetSymbolAddress((void**)&S, g_S);
    cudaGetSymbolAddress((void**)&Xh, g_Xh);   cudaGetSymbolAddress((void**)&Xl, g_Xl);
    cudaGetSymbolAddress((void**)&Wqh, g_Wqh); cudaGetSymbolAddress((void**)&Wql, g_Wql);
    cudaGetSymbolAddress((void**)&Wkh, g_Wkh); cudaGetSymbolAddress((void**)&Wkl, g_Wkl);
    cudaGetSymbolAddress((void**)&Wvh, g_Wvh); cudaGetSymbolAddress((void**)&Wvl, g_Wvl);
    cudaGetSymbolAddress((void**)&Qh, g_Qh);   cudaGetSymbolAddress((void**)&Ql, g_Ql);
    cudaGetSymbolAddress((void**)&Kh, g_Kh);   cudaGetSymbolAddress((void**)&Kl, g_Kl);
    cudaGetSymbolAddress((void**)&Vth, g_Vth); cudaGetSymbolAddress((void**)&Vtl, g_Vtl);
    cudaGetSymbolAddress((void**)&Ph, g_Ph);   cudaGetSymbolAddress((void**)&Pl, g_Pl);

    cudaFuncSetAttribute(hmma_gemm_nt,
                         cudaFuncAttributeMaxDynamicSharedMemorySize, GEMM_SMEM);

    const int nXd4 = SEQ * DMODEL / 4;

    // 1. Split X; transpose+split weights.
    split_kernel<<<(nXd4 + 255) / 256, 256>>>(x, Xh, Xl, nXd4);
    dim3 tb(32, 8);
    transpose_split_kernel<<<dim3(DMODEL / 32, DMODEL / 32), tb>>>(wq, Wqh, Wql, DMODEL, DMODEL);
    transpose_split_kernel<<<dim3(DMODEL / 32, DMODEL / 32), tb>>>(wk, Wkh, Wkl, DMODEL, DMODEL);
    transpose_split_kernel<<<dim3(DMODEL / 32, DMODEL / 32), tb>>>(wv, Wvh, Wvl, DMODEL, DMODEL);

    // 2. Projections: Q/K/V = X @ W  (B given as W^T [N,K])
    dim3 gp(DMODEL / 256, SEQ / 128);   // (4, 32)
    hmma_gemm_nt<<<gp, 256, GEMM_SMEM>>>(Xh, Xl, Wqh, Wql, Q, DMODEL, DMODEL);
    hmma_gemm_nt<<<gp, 256, GEMM_SMEM>>>(Xh, Xl, Wkh, Wkl, K, DMODEL, DMODEL);
    hmma_gemm_nt<<<gp, 256, GEMM_SMEM>>>(Xh, Xl, Wvh, Wvl, V, DMODEL, DMODEL);

    // 3. Split Q and K; transpose+split V.
    split_kernel<<<(nXd4 + 255) / 256, 256>>>(Q, Qh, Ql, nXd4);
    split_kernel<<<(nXd4 + 255) / 256, 256>>>(K, Kh, Kl, nXd4);
    transpose_split_kernel<<<dim3(DMODEL / 32, SEQ / 32), tb>>>(V, Vth, Vtl, SEQ, DMODEL);

    // 4. Scores: S = Q @ K^T
    dim3 gs(SEQ / 256, SEQ / 128);      // (16, 32)
    hmma_gemm_nt<<<gs, 256, GEMM_SMEM>>>(Qh, Ql, Kh, Kl, S, DMODEL, SEQ);

    // 5. Softmax(S/32) -> split P
    softmax_split_kernel<<<SEQ, 256>>>(S, Ph, Pl);

    // 6. Context: out = P @ V   (B = V^T [DMODEL, SEQ])
    dim3 gc(DMODEL / 256, SEQ / 128);   // (4, 32)
    hmma_gemm_nt<<<gc, 256, GEMM_SMEM>>>(Ph, Pl, Vth, Vtl, out, SEQ, DMODEL);
}